// round 16
// baseline (speedup 1.0000x reference)
#include <cuda_runtime.h>
#include <cuda_fp16.h>
#include <math.h>
#include <stdint.h>

#define NN 50000
#define EE 800000
#define DD 256
#define HC 256
#define LL 3
#define SCALE 0.125f

// ---------------- scratch ----------------------------------------------------
__device__ __half g_qs[NN * 512];          // per node: [q(256) | s(256)] fp16
__device__ __half g_kv[NN * 512];          // per node: [k(256) | v(256)] fp16
__device__ __half g_Ah[NN * 256];          // current layer input features fp16
__device__ __half g_Wh[LL * 4 * 256 * 256];// fp16 weights [l][q,k,v,s][k][n]
__device__ int    g_rowptr[NN + 1];
__device__ int    g_cnt[NN];
__device__ int    g_offs[NN];
__device__ int    g_col[EE];
__device__ int    g_bsum[64];
__device__ int    g_boff[64];

// ---------------- converts ----------------------------------------------------
// one layer's 4 matrices (4*65536 elems)
__global__ void convert_w_layer_kernel(const float* __restrict__ Wq, const float* __restrict__ Wk,
                                       const float* __restrict__ Wv, const float* __restrict__ Ws,
                                       __half* __restrict__ Whl, int l) {
    int idx = blockIdx.x * blockDim.x + threadIdx.x;   // over 4*65536
    if (idx < 4 * 65536) {
        int w = idx >> 16;
        int off = idx & 65535;
        const float* src = (w == 0) ? Wq : (w == 1) ? Wk : (w == 2) ? Wv : Ws;
        Whl[idx] = __float2half(src[l * 65536 + off]);
    }
}

// vectorized: 8 elems/thread
__global__ void convert_x_kernel(const float* __restrict__ x, __half* __restrict__ Ah) {
    int idx = blockIdx.x * blockDim.x + threadIdx.x;   // over NN*256/8
    if (idx < NN * 32) {
        const float4* src = (const float4*)(x + idx * 8);
        float4 a = src[0], b = src[1];
        uint4 o;
        *(__half2*)&o.x = __floats2half2_rn(a.x, a.y);
        *(__half2*)&o.y = __floats2half2_rn(a.z, a.w);
        *(__half2*)&o.z = __floats2half2_rn(b.x, b.y);
        *(__half2*)&o.w = __floats2half2_rn(b.z, b.w);
        *(uint4*)(Ah + idx * 8) = o;
    }
}

// ---------------- CSR construction ------------------------------------------
__global__ void zero_counts_kernel() {
    int i = blockIdx.x * blockDim.x + threadIdx.x;
    if (i < NN) { g_cnt[i] = 0; g_offs[i] = 0; }
}

__global__ void count_dst_kernel(const int* __restrict__ edge_index) {
    int e = blockIdx.x * blockDim.x + threadIdx.x;
    if (e < EE) atomicAdd(&g_cnt[edge_index[EE + e]], 1);
}

__global__ void scan1_kernel() {
    __shared__ int warpsum[32];
    int tid = threadIdx.x, lane = tid & 31, wid = tid >> 5;
    int i = blockIdx.x * 1024 + tid;
    int val = (i < NN) ? g_cnt[i] : 0;
    int x = val;
    #pragma unroll
    for (int off = 1; off < 32; off <<= 1) {
        int y = __shfl_up_sync(0xffffffff, x, off);
        if (lane >= off) x += y;
    }
    if (lane == 31) warpsum[wid] = x;
    __syncthreads();
    if (wid == 0) {
        int w = warpsum[lane];
        #pragma unroll
        for (int off = 1; off < 32; off <<= 1) {
            int y = __shfl_up_sync(0xffffffff, w, off);
            if (lane >= off) w += y;
        }
        warpsum[lane] = w;
    }
    __syncthreads();
    int incl = x + (wid > 0 ? warpsum[wid - 1] : 0);
    if (i < NN) g_rowptr[i] = incl - val;
    if (tid == 1023) g_bsum[blockIdx.x] = incl;
}

__global__ void scan2_kernel(int nblocks) {
    if (threadIdx.x == 0) {
        int run = 0;
        for (int b = 0; b < nblocks; b++) {
            g_boff[b] = run;
            run += g_bsum[b];
        }
        g_rowptr[NN] = run;
    }
}

__global__ void scan3_kernel() {
    int i = blockIdx.x * 1024 + threadIdx.x;
    if (i < NN) g_rowptr[i] += g_boff[blockIdx.x];
}

__global__ void fill_csr_kernel(const int* __restrict__ edge_index) {
    int e = blockIdx.x * blockDim.x + threadIdx.x;
    if (e < EE) {
        int s = edge_index[e];
        int d = edge_index[EE + e];
        int pos = g_rowptr[d] + atomicAdd(&g_offs[d], 1);
        g_col[pos] = s;
    }
}

// ---------------- FP16 GEMM: 3-stage cp.async pipeline, BK=32 ----------------
#define BM 128
#define BN 128
#define BK 32
#define ASTR 40
#define BSTR 136
#define STAGES 3
#define SA_STAGE (BM * ASTR)
#define SB_STAGE (BK * BSTR)
#define GEMM_SMEM ((STAGES * (SA_STAGE + SB_STAGE)) * 2)   // 56832 B

__device__ __forceinline__ void cp_async16(uint32_t dst, const void* src) {
    asm volatile("cp.async.cg.shared.global [%0], [%1], 16;" :: "r"(dst), "l"(src));
}

__global__ __launch_bounds__(256, 2)
void gemm_qkvs_kernel(const __half* __restrict__ Ah,
                      const __half* __restrict__ Wl,
                      const float* __restrict__ b0, const float* __restrict__ b1,
                      const float* __restrict__ b2, const float* __restrict__ b3,
                      __half* __restrict__ qs, __half* __restrict__ kv, int M) {
    extern __shared__ __half smh[];
    __half* sA = smh;
    __half* sB = smh + STAGES * SA_STAGE;

    const int which = blockIdx.x >> 1;
    const __half* B   = Wl + which * 65536;
    const float* bias = (which == 0) ? b0 : (which == 1) ? b1 : (which == 2) ? b2 : b3;

    const int tid  = threadIdx.x;
    const int lane = tid & 31;
    const int wid  = tid >> 5;
    const int wm   = (wid & 3) * 32;
    const int wn   = (wid >> 2) * 64;
    const int brow = blockIdx.y * BM;
    const int bcol = (blockIdx.x & 1) * BN;

    float c[2][8][4];
    #pragma unroll
    for (int i = 0; i < 2; i++)
        #pragma unroll
        for (int j = 0; j < 8; j++)
            #pragma unroll
            for (int r = 0; r < 4; r++) c[i][j][r] = 0.f;

    const __half* asrc[2];
    const __half* bsrc[2];
    int aoff[2], boff[2];
    #pragma unroll
    for (int i = 0; i < 2; i++) {
        int ci = tid + i * 256;
        int ar = ci >> 2, akc = (ci & 3) * 8;
        int br = ci >> 4, bnc = (ci & 15) * 8;
        int gr = brow + ar;
        if (gr >= M) gr = M - 1;
        asrc[i] = Ah + (size_t)gr * 256 + akc;
        bsrc[i] = B + (size_t)br * 256 + bcol + bnc;
        aoff[i] = ar * ASTR + akc;
        boff[i] = br * BSTR + bnc;
    }

    uint32_t sabase = (uint32_t)__cvta_generic_to_shared(sA);
    uint32_t sbbase = (uint32_t)__cvta_generic_to_shared(sB);

    const int NSTEP = 256 / BK;   // 8

    #pragma unroll
    for (int p = 0; p < 2; p++) {
        int k0 = p * BK;
        #pragma unroll
        for (int i = 0; i < 2; i++) {
            cp_async16(sabase + (p * SA_STAGE + aoff[i]) * 2, asrc[i] + k0);
            cp_async16(sbbase + (p * SB_STAGE + boff[i]) * 2, bsrc[i] + (size_t)k0 * 256);
        }
        asm volatile("cp.async.commit_group;");
    }

    const int lrow = lane & 15;
    const int lhi  = (lane >> 4) * 8;

    int st_c = 0;
    int st_p = 2;
    for (int t = 0; t < NSTEP; t++) {
        asm volatile("cp.async.wait_group 1;");
        __syncthreads();

        if (t + 2 < NSTEP) {
            int k0 = (t + 2) * BK;
            #pragma unroll
            for (int i = 0; i < 2; i++) {
                cp_async16(sabase + (st_p * SA_STAGE + aoff[i]) * 2, asrc[i] + k0);
                cp_async16(sbbase + (st_p * SB_STAGE + boff[i]) * 2, bsrc[i] + (size_t)k0 * 256);
            }
        }
        asm volatile("cp.async.commit_group;");

        uint32_t abase = sabase + st_c * SA_STAGE * 2;
        uint32_t bbase = sbbase + st_c * SB_STAGE * 2;

        #pragma unroll
        for (int kb = 0; kb < BK; kb += 16) {
            uint32_t af[2][4];
            #pragma unroll
            for (int mt = 0; mt < 2; mt++) {
                uint32_t addr = abase + ((wm + mt * 16 + lrow) * ASTR + kb + lhi) * 2;
                asm volatile("ldmatrix.sync.aligned.m8n8.x4.shared.b16 {%0,%1,%2,%3}, [%4];"
                             : "=r"(af[mt][0]), "=r"(af[mt][1]),
                               "=r"(af[mt][2]), "=r"(af[mt][3])
                             : "r"(addr));
            }
            uint32_t bf[8][2];
            #pragma unroll
            for (int nt2 = 0; nt2 < 4; nt2++) {
                uint32_t addr = bbase + ((kb + lrow) * BSTR + wn + nt2 * 16 + lhi) * 2;
                asm volatile("ldmatrix.sync.aligned.m8n8.x4.trans.shared.b16 {%0,%1,%2,%3}, [%4];"
                             : "=r"(bf[2 * nt2][0]), "=r"(bf[2 * nt2][1]),
                               "=r"(bf[2 * nt2 + 1][0]), "=r"(bf[2 * nt2 + 1][1])
                             : "r"(addr));
            }
            #pragma unroll
            for (int mt = 0; mt < 2; mt++)
                #pragma unroll
                for (int nt = 0; nt < 8; nt++) {
                    asm volatile(
                        "mma.sync.aligned.m16n8k16.row.col.f32.f16.f16.f32 "
                        "{%0,%1,%2,%3}, {%4,%5,%6,%7}, {%8,%9}, {%0,%1,%2,%3};"
                        : "+f"(c[mt][nt][0]), "+f"(c[mt][nt][1]),
                          "+f"(c[mt][nt][2]), "+f"(c[mt][nt][3])
                        : "r"(af[mt][0]), "r"(af[mt][1]),
                          "r"(af[mt][2]), "r"(af[mt][3]),
                          "r"(bf[nt][0]), "r"(bf[nt][1]));
                }
        }

        st_c = (st_c == STAGES - 1) ? 0 : st_c + 1;
        st_p = (st_p == STAGES - 1) ? 0 : st_p + 1;
    }

    // epilogue: uniform fp16 stores
    const int l4 = lane & 3, l8 = lane >> 2;
    __half* dst = ((which == 0) || (which == 3)) ? qs : kv;
    dst += ((which == 2) || (which == 3)) ? 256 : 0;
    #pragma unroll
    for (int mt = 0; mt < 2; mt++) {
        #pragma unroll
        for (int half = 0; half < 2; half++) {
            int grow = brow + wm + mt * 16 + l8 + half * 8;
            if (grow < M) {
                #pragma unroll
                for (int nt = 0; nt < 8; nt++) {
                    int gcol = bcol + wn + nt * 8 + 2 * l4;
                    float ox = c[mt][nt][half * 2 + 0] + bias[gcol + 0];
                    float oy = c[mt][nt][half * 2 + 1] + bias[gcol + 1];
                    *(__half2*)(dst + (size_t)grow * 512 + gcol) = __floats2half2_rn(ox, oy);
                }
            }
        }
    }
}

// ---------------- edge attention ---------------------------------------------
__global__ void edge_attn_kernel(const __half* __restrict__ qs,
                                 const __half* __restrict__ kv,
                                 float* __restrict__ out,
                                 __half* __restrict__ ah) {
    int warp = (blockIdx.x * blockDim.x + threadIdx.x) >> 5;
    if (warp >= NN) return;
    int lane = threadIdx.x & 31;
    const int ch = lane * 8;
    const __half* nb = qs + (size_t)warp * 512;

    uint4 qr = *(const uint4*)(nb + ch);
    float2 qa = __half22float2(*(__half2*)&qr.x);
    float2 qb = __half22float2(*(__half2*)&qr.y);
    float2 qc = __half22float2(*(__half2*)&qr.z);
    float2 qd = __half22float2(*(__half2*)&qr.w);
    float4 q0 = make_float4(qa.x, qa.y, qb.x, qb.y);
    float4 q1 = make_float4(qc.x, qc.y, qd.x, qd.y);

    float d = 0.f;
    float acc[8];
    #pragma unroll
    for (int i = 0; i < 8; i++) acc[i] = 0.f;

    const int e0 = g_rowptr[warp], e1 = g_rowptr[warp + 1];
    int e = e0;

    #define LOADKV(S, KK, VV)                                                  \
        {                                                                      \
            const __half* p_ = kv + (size_t)(S) * 512 + ch;                    \
            KK = *(const uint4*)p_;                                            \
            VV = *(const uint4*)(p_ + 256);                                    \
        }
    #define DOT8(KK, P)                                                        \
        {                                                                      \
            float2 h0_ = __half22float2(*(__half2*)&KK.x);                     \
            float2 h1_ = __half22float2(*(__half2*)&KK.y);                     \
            float2 h2_ = __half22float2(*(__half2*)&KK.z);                     \
            float2 h3_ = __half22float2(*(__half2*)&KK.w);                     \
            P = q0.x*h0_.x + q0.y*h0_.y + q0.z*h1_.x + q0.w*h1_.y              \
              + q1.x*h2_.x + q1.y*h2_.y + q1.z*h3_.x + q1.w*h3_.y;             \
        }
    #define ACCV(VV, PE)                                                       \
        {                                                                      \
            float2 h0_ = __half22float2(*(__half2*)&VV.x);                     \
            float2 h1_ = __half22float2(*(__half2*)&VV.y);                     \
            float2 h2_ = __half22float2(*(__half2*)&VV.z);                     \
            float2 h3_ = __half22float2(*(__half2*)&VV.w);                     \
            acc[0] += PE * h0_.x; acc[1] += PE * h0_.y;                        \
            acc[2] += PE * h1_.x; acc[3] += PE * h1_.y;                        \
            acc[4] += PE * h2_.x; acc[5] += PE * h2_.y;                        \
            acc[6] += PE * h3_.x; acc[7] += PE * h3_.y;                        \
        }

    for (; e + 3 < e1; e += 4) {
        int s0 = g_col[e], s1 = g_col[e + 1], s2 = g_col[e + 2], s3 = g_col[e + 3];
        uint4 k0v, k1v, k2v, k3v, v0v, v1v, v2v, v3v;
        LOADKV(s0, k0v, v0v);
        LOADKV(s1, k1v, v1v);
        LOADKV(s2, k2v, v2v);
        LOADKV(s3, k3v, v3v);

        float p0, p1, p2, p3;
        DOT8(k0v, p0);
        DOT8(k1v, p1);
        DOT8(k2v, p2);
        DOT8(k3v, p3);
        p0 += __shfl_xor_sync(0xffffffff, p0, 1);
        p1 += __shfl_xor_sync(0xffffffff, p1, 1);
        p2 += __shfl_xor_sync(0xffffffff, p2, 1);
        p3 += __shfl_xor_sync(0xffffffff, p3, 1);
        p0 += __shfl_xor_sync(0xffffffff, p0, 2);
        p1 += __shfl_xor_sync(0xffffffff, p1, 2);
        p2 += __shfl_xor_sync(0xffffffff, p2, 2);
        p3 += __shfl_xor_sync(0xffffffff, p3, 2);
        p0 += __shfl_xor_sync(0xffffffff, p0, 4);
        p1 += __shfl_xor_sync(0xffffffff, p1, 4);
        p2 += __shfl_xor_sync(0xffffffff, p2, 4);
        p3 += __shfl_xor_sync(0xffffffff, p3, 4);

        float pe0 = __expf(fminf(p0 * SCALE, 85.f));
        float pe1 = __expf(fminf(p1 * SCALE, 85.f));
        float pe2 = __expf(fminf(p2 * SCALE, 85.f));
        float pe3 = __expf(fminf(p3 * SCALE, 85.f));
        d += pe0 + pe1 + pe2 + pe3;
        ACCV(v0v, pe0);
        ACCV(v1v, pe1);
        ACCV(v2v, pe2);
        ACCV(v3v, pe3);
    }

    for (; e < e1; e++) {
        int s0 = g_col[e];
        uint4 kk, vv;
        LOADKV(s0, kk, vv);
        float p;
        DOT8(kk, p);
        p += __shfl_xor_sync(0xffffffff, p, 1);
        p += __shfl_xor_sync(0xffffffff, p, 2);
        p += __shfl_xor_sync(0xffffffff, p, 4);
        float pe = __expf(fminf(p * SCALE, 85.f));
        d += pe;
        ACCV(vv, pe);
    }

    float inv = (d > 0.f) ? 1.f / d : 0.f;
    uint4 sr = *(const uint4*)(nb + 256 + ch);
    float2 sa = __half22float2(*(__half2*)&sr.x);
    float2 sb = __half22float2(*(__half2*)&sr.y);
    float2 sc = __half22float2(*(__half2*)&sr.z);
    float2 sd = __half22float2(*(__half2*)&sr.w);

    float4 o0, o1;
    o0.x = fmaxf(acc[0] * inv + sa.x, 0.f);
    o0.y = fmaxf(acc[1] * inv + sa.y, 0.f);
    o0.z = fmaxf(acc[2] * inv + sb.x, 0.f);
    o0.w = fmaxf(acc[3] * inv + sb.y, 0.f);
    o1.x = fmaxf(acc[4] * inv + sc.x, 0.f);
    o1.y = fmaxf(acc[5] * inv + sc.y, 0.f);
    o1.z = fmaxf(acc[6] * inv + sd.x, 0.f);
    o1.w = fmaxf(acc[7] * inv + sd.y, 0.f);

    if (ah) {
        uint4 hp;
        *(__half2*)&hp.x = __floats2half2_rn(o0.x, o0.y);
        *(__half2*)&hp.y = __floats2half2_rn(o0.z, o0.w);
        *(__half2*)&hp.z = __floats2half2_rn(o1.x, o1.y);
        *(__half2*)&hp.w = __floats2half2_rn(o1.z, o1.w);
        *(uint4*)(ah + (size_t)warp * 256 + ch) = hp;
    }

    if (out) {
        float* op = out + (size_t)warp * 256 + ch;
        *(float4*)op       = o0;
        *(float4*)(op + 4) = o1;
    }
}

// ---------------- launch ------------------------------------------------------
extern "C" void kernel_launch(void* const* d_in, const int* in_sizes, int n_in,
                              void* d_out, int out_size) {
    const float* x   = (const float*)d_in[0];
    const int*   ei  = (const int*)d_in[1];
    const float* Wq  = (const float*)d_in[2];
    const float* bq  = (const float*)d_in[3];
    const float* Wk  = (const float*)d_in[4];
    const float* bk  = (const float*)d_in[5];
    const float* Wv  = (const float*)d_in[6];
    const float* bv  = (const float*)d_in[7];
    const float* Ws  = (const float*)d_in[8];
    const float* bs  = (const float*)d_in[9];
    float* out = (float*)d_out;

    __half *qsp, *kvp, *ah, *wh;
    cudaGetSymbolAddress((void**)&qsp, g_qs);
    cudaGetSymbolAddress((void**)&kvp, g_kv);
    cudaGetSymbolAddress((void**)&ah,  g_Ah);
    cudaGetSymbolAddress((void**)&wh,  g_Wh);

    static bool init_done = false;
    static cudaStream_t s_aux;
    static cudaEvent_t ev_fork, ev_join;
    static cudaEvent_t ev_wl[LL];
    if (!init_done) {
        cudaFuncSetAttribute(gemm_qkvs_kernel,
                             cudaFuncAttributeMaxDynamicSharedMemorySize, GEMM_SMEM);
        cudaStreamCreateWithFlags(&s_aux, cudaStreamNonBlocking);
        cudaEventCreateWithFlags(&ev_fork, cudaEventDisableTiming);
        cudaEventCreateWithFlags(&ev_join, cudaEventDisableTiming);
        for (int l = 0; l < LL; l++)
            cudaEventCreateWithFlags(&ev_wl[l], cudaEventDisableTiming);
        init_done = true;
    }

    const int SCAN_BLOCKS = (NN + 1023) / 1024;   // 49

    // fork: per-layer weight converts + CSR build on aux stream
    cudaEventRecord(ev_fork, 0);
    cudaStreamWaitEvent(s_aux, ev_fork, 0);

    for (int l = 0; l < LL; l++) {
        convert_w_layer_kernel<<<(4 * 65536 + 255) / 256, 256, 0, s_aux>>>(
            Wq, Wk, Wv, Ws, wh + (size_t)l * 4 * 65536, l);
        cudaEventRecord(ev_wl[l], s_aux);
    }
    zero_counts_kernel<<<(NN + 255) / 256, 256, 0, s_aux>>>();
    count_dst_kernel<<<(EE + 255) / 256, 256, 0, s_aux>>>(ei);
    scan1_kernel<<<SCAN_BLOCKS, 1024, 0, s_aux>>>();
    scan2_kernel<<<1, 32, 0, s_aux>>>(SCAN_BLOCKS);
    scan3_kernel<<<SCAN_BLOCKS, 1024, 0, s_aux>>>();
    fill_csr_kernel<<<(EE + 255) / 256, 256, 0, s_aux>>>(ei);
    cudaEventRecord(ev_join, s_aux);

    // main: feature convert, then layers
    convert_x_kernel<<<(NN * 32 + 255) / 256, 256>>>(x, ah);

    dim3 gemm_grid(8, (NN + BM - 1) / BM);
    int edge_blocks = (NN + 7) / 8;

    for (int l = 0; l < LL; l++) {
        cudaStreamWaitEvent(0, ev_wl[l], 0);   // this layer's weights ready
        gemm_qkvs_kernel<<<gemm_grid, 256, GEMM_SMEM>>>(
            ah, wh + (size_t)l * 4 * 65536,
            bq + l * HC, bk + l * HC, bv + l * HC, bs + l * HC,
            qsp, kvp, NN);

        if (l == 0) cudaStreamWaitEvent(0, ev_join, 0);   // CSR ready before first edge pass

        float* hout = (l == LL - 1) ? out : nullptr;
        __half* hah = (l == LL - 1) ? nullptr : ah;       // last layer: skip dead ah write
        edge_attn_kernel<<<edge_blocks, 256>>>(qsp, kvp, hout, hah);
    }
}

// round 17
// speedup vs baseline: 1.0219x; 1.0219x over previous
#include <cuda_runtime.h>
#include <cuda_fp16.h>
#include <math.h>
#include <stdint.h>

#define NN 50000
#define EE 800000
#define DD 256
#define HC 256
#define LL 3
#define SCALE 0.125f

// ---------------- scratch ----------------------------------------------------
__device__ __half g_qs[NN * 512];          // per node: [q(256) | s(256)] fp16
__device__ __half g_kv[NN * 512];          // per node: [k(256) | v(256)] fp16
__device__ __half g_Ah[NN * 256];          // current layer input features fp16
__device__ __half g_Wh[LL * 4 * 256 * 256];// fp16 weights [l][q,k,v,s][k][n]
__device__ int    g_rowptr[NN + 1];
__device__ int    g_cnt[NN];
__device__ int    g_offs[NN];
__device__ int    g_col[EE];
__device__ int    g_bsum[64];
__device__ int    g_boff[64];

// ---------------- converts ----------------------------------------------------
__global__ void convert_w_kernel(const float* __restrict__ Wq, const float* __restrict__ Wk,
                                 const float* __restrict__ Wv, const float* __restrict__ Ws,
                                 __half* __restrict__ Wh) {
    int idx = blockIdx.x * blockDim.x + threadIdx.x;
    if (idx < LL * 4 * 65536) {
        int l = idx >> 18;
        int w = (idx >> 16) & 3;
        int off = idx & 65535;
        const float* src = (w == 0) ? Wq : (w == 1) ? Wk : (w == 2) ? Wv : Ws;
        Wh[idx] = __float2half(src[l * 65536 + off]);
    }
}

// vectorized: 8 elems/thread
__global__ void convert_x_kernel(const float* __restrict__ x, __half* __restrict__ Ah) {
    int idx = blockIdx.x * blockDim.x + threadIdx.x;   // over NN*256/8
    if (idx < NN * 32) {
        const float4* src = (const float4*)(x + idx * 8);
        float4 a = src[0], b = src[1];
        uint4 o;
        *(__half2*)&o.x = __floats2half2_rn(a.x, a.y);
        *(__half2*)&o.y = __floats2half2_rn(a.z, a.w);
        *(__half2*)&o.z = __floats2half2_rn(b.x, b.y);
        *(__half2*)&o.w = __floats2half2_rn(b.z, b.w);
        *(uint4*)(Ah + idx * 8) = o;
    }
}

// ---------------- CSR construction ------------------------------------------
__global__ void zero_counts_kernel() {
    int i = blockIdx.x * blockDim.x + threadIdx.x;
    if (i < NN) { g_cnt[i] = 0; g_offs[i] = 0; }
}

__global__ void count_dst_kernel(const int* __restrict__ edge_index) {
    int e = blockIdx.x * blockDim.x + threadIdx.x;
    if (e < EE) atomicAdd(&g_cnt[edge_index[EE + e]], 1);
}

__global__ void scan1_kernel() {
    __shared__ int warpsum[32];
    int tid = threadIdx.x, lane = tid & 31, wid = tid >> 5;
    int i = blockIdx.x * 1024 + tid;
    int val = (i < NN) ? g_cnt[i] : 0;
    int x = val;
    #pragma unroll
    for (int off = 1; off < 32; off <<= 1) {
        int y = __shfl_up_sync(0xffffffff, x, off);
        if (lane >= off) x += y;
    }
    if (lane == 31) warpsum[wid] = x;
    __syncthreads();
    if (wid == 0) {
        int w = warpsum[lane];
        #pragma unroll
        for (int off = 1; off < 32; off <<= 1) {
            int y = __shfl_up_sync(0xffffffff, w, off);
            if (lane >= off) w += y;
        }
        warpsum[lane] = w;
    }
    __syncthreads();
    int incl = x + (wid > 0 ? warpsum[wid - 1] : 0);
    if (i < NN) g_rowptr[i] = incl - val;
    if (tid == 1023) g_bsum[blockIdx.x] = incl;
}

__global__ void scan2_kernel(int nblocks) {
    if (threadIdx.x == 0) {
        int run = 0;
        for (int b = 0; b < nblocks; b++) {
            g_boff[b] = run;
            run += g_bsum[b];
        }
        g_rowptr[NN] = run;
    }
}

__global__ void scan3_kernel() {
    int i = blockIdx.x * 1024 + threadIdx.x;
    if (i < NN) g_rowptr[i] += g_boff[blockIdx.x];
}

__global__ void fill_csr_kernel(const int* __restrict__ edge_index) {
    int e = blockIdx.x * blockDim.x + threadIdx.x;
    if (e < EE) {
        int s = edge_index[e];
        int d = edge_index[EE + e];
        int pos = g_rowptr[d] + atomicAdd(&g_offs[d], 1);
        g_col[pos] = s;
    }
}

// ---------------- FP16 GEMM: 3-stage cp.async pipeline, BK=32 ----------------
#define BM 128
#define BN 128
#define BK 32
#define ASTR 40
#define BSTR 136
#define STAGES 3
#define SA_STAGE (BM * ASTR)
#define SB_STAGE (BK * BSTR)
#define GEMM_SMEM ((STAGES * (SA_STAGE + SB_STAGE)) * 2)   // 56832 B

__device__ __forceinline__ void cp_async16(uint32_t dst, const void* src) {
    asm volatile("cp.async.cg.shared.global [%0], [%1], 16;" :: "r"(dst), "l"(src));
}

__global__ __launch_bounds__(256, 2)
void gemm_qkvs_kernel(const __half* __restrict__ Ah,
                      const __half* __restrict__ Wl,
                      const float* __restrict__ b0, const float* __restrict__ b1,
                      const float* __restrict__ b2, const float* __restrict__ b3,
                      __half* __restrict__ qs, __half* __restrict__ kv, int M) {
    extern __shared__ __half smh[];
    __half* sA = smh;
    __half* sB = smh + STAGES * SA_STAGE;

    const int which = blockIdx.x >> 1;
    const __half* B   = Wl + which * 65536;
    const float* bias = (which == 0) ? b0 : (which == 1) ? b1 : (which == 2) ? b2 : b3;

    const int tid  = threadIdx.x;
    const int lane = tid & 31;
    const int wid  = tid >> 5;
    const int wm   = (wid & 3) * 32;
    const int wn   = (wid >> 2) * 64;
    const int brow = blockIdx.y * BM;
    const int bcol = (blockIdx.x & 1) * BN;

    float c[2][8][4];
    #pragma unroll
    for (int i = 0; i < 2; i++)
        #pragma unroll
        for (int j = 0; j < 8; j++)
            #pragma unroll
            for (int r = 0; r < 4; r++) c[i][j][r] = 0.f;

    const __half* asrc[2];
    const __half* bsrc[2];
    int aoff[2], boff[2];
    #pragma unroll
    for (int i = 0; i < 2; i++) {
        int ci = tid + i * 256;
        int ar = ci >> 2, akc = (ci & 3) * 8;
        int br = ci >> 4, bnc = (ci & 15) * 8;
        int gr = brow + ar;
        if (gr >= M) gr = M - 1;
        asrc[i] = Ah + (size_t)gr * 256 + akc;
        bsrc[i] = B + (size_t)br * 256 + bcol + bnc;
        aoff[i] = ar * ASTR + akc;
        boff[i] = br * BSTR + bnc;
    }

    uint32_t sabase = (uint32_t)__cvta_generic_to_shared(sA);
    uint32_t sbbase = (uint32_t)__cvta_generic_to_shared(sB);

    const int NSTEP = 256 / BK;   // 8

    #pragma unroll
    for (int p = 0; p < 2; p++) {
        int k0 = p * BK;
        #pragma unroll
        for (int i = 0; i < 2; i++) {
            cp_async16(sabase + (p * SA_STAGE + aoff[i]) * 2, asrc[i] + k0);
            cp_async16(sbbase + (p * SB_STAGE + boff[i]) * 2, bsrc[i] + (size_t)k0 * 256);
        }
        asm volatile("cp.async.commit_group;");
    }

    const int lrow = lane & 15;
    const int lhi  = (lane >> 4) * 8;

    int st_c = 0;
    int st_p = 2;
    for (int t = 0; t < NSTEP; t++) {
        asm volatile("cp.async.wait_group 1;");
        __syncthreads();

        if (t + 2 < NSTEP) {
            int k0 = (t + 2) * BK;
            #pragma unroll
            for (int i = 0; i < 2; i++) {
                cp_async16(sabase + (st_p * SA_STAGE + aoff[i]) * 2, asrc[i] + k0);
                cp_async16(sbbase + (st_p * SB_STAGE + boff[i]) * 2, bsrc[i] + (size_t)k0 * 256);
            }
        }
        asm volatile("cp.async.commit_group;");

        uint32_t abase = sabase + st_c * SA_STAGE * 2;
        uint32_t bbase = sbbase + st_c * SB_STAGE * 2;

        #pragma unroll
        for (int kb = 0; kb < BK; kb += 16) {
            uint32_t af[2][4];
            #pragma unroll
            for (int mt = 0; mt < 2; mt++) {
                uint32_t addr = abase + ((wm + mt * 16 + lrow) * ASTR + kb + lhi) * 2;
                asm volatile("ldmatrix.sync.aligned.m8n8.x4.shared.b16 {%0,%1,%2,%3}, [%4];"
                             : "=r"(af[mt][0]), "=r"(af[mt][1]),
                               "=r"(af[mt][2]), "=r"(af[mt][3])
                             : "r"(addr));
            }
            uint32_t bf[8][2];
            #pragma unroll
            for (int nt2 = 0; nt2 < 4; nt2++) {
                uint32_t addr = bbase + ((kb + lrow) * BSTR + wn + nt2 * 16 + lhi) * 2;
                asm volatile("ldmatrix.sync.aligned.m8n8.x4.trans.shared.b16 {%0,%1,%2,%3}, [%4];"
                             : "=r"(bf[2 * nt2][0]), "=r"(bf[2 * nt2][1]),
                               "=r"(bf[2 * nt2 + 1][0]), "=r"(bf[2 * nt2 + 1][1])
                             : "r"(addr));
            }
            #pragma unroll
            for (int mt = 0; mt < 2; mt++)
                #pragma unroll
                for (int nt = 0; nt < 8; nt++) {
                    asm volatile(
                        "mma.sync.aligned.m16n8k16.row.col.f32.f16.f16.f32 "
                        "{%0,%1,%2,%3}, {%4,%5,%6,%7}, {%8,%9}, {%0,%1,%2,%3};"
                        : "+f"(c[mt][nt][0]), "+f"(c[mt][nt][1]),
                          "+f"(c[mt][nt][2]), "+f"(c[mt][nt][3])
                        : "r"(af[mt][0]), "r"(af[mt][1]),
                          "r"(af[mt][2]), "r"(af[mt][3]),
                          "r"(bf[nt][0]), "r"(bf[nt][1]));
                }
        }

        st_c = (st_c == STAGES - 1) ? 0 : st_c + 1;
        st_p = (st_p == STAGES - 1) ? 0 : st_p + 1;
    }

    // epilogue: uniform fp16 stores
    const int l4 = lane & 3, l8 = lane >> 2;
    __half* dst = ((which == 0) || (which == 3)) ? qs : kv;
    dst += ((which == 2) || (which == 3)) ? 256 : 0;
    #pragma unroll
    for (int mt = 0; mt < 2; mt++) {
        #pragma unroll
        for (int half = 0; half < 2; half++) {
            int grow = brow + wm + mt * 16 + l8 + half * 8;
            if (grow < M) {
                #pragma unroll
                for (int nt = 0; nt < 8; nt++) {
                    int gcol = bcol + wn + nt * 8 + 2 * l4;
                    float ox = c[mt][nt][half * 2 + 0] + bias[gcol + 0];
                    float oy = c[mt][nt][half * 2 + 1] + bias[gcol + 1];
                    *(__half2*)(dst + (size_t)grow * 512 + gcol) = __floats2half2_rn(ox, oy);
                }
            }
        }
    }
}

// ---------------- edge attention ---------------------------------------------
__global__ void edge_attn_kernel(const __half* __restrict__ qs,
                                 const __half* __restrict__ kv,
                                 float* __restrict__ out,
                                 __half* __restrict__ ah) {
    int warp = (blockIdx.x * blockDim.x + threadIdx.x) >> 5;
    if (warp >= NN) return;
    int lane = threadIdx.x & 31;
    const int ch = lane * 8;
    const __half* nb = qs + (size_t)warp * 512;

    uint4 qr = *(const uint4*)(nb + ch);
    float2 qa = __half22float2(*(__half2*)&qr.x);
    float2 qb = __half22float2(*(__half2*)&qr.y);
    float2 qc = __half22float2(*(__half2*)&qr.z);
    float2 qd = __half22float2(*(__half2*)&qr.w);
    float4 q0 = make_float4(qa.x, qa.y, qb.x, qb.y);
    float4 q1 = make_float4(qc.x, qc.y, qd.x, qd.y);

    float d = 0.f;
    float acc[8];
    #pragma unroll
    for (int i = 0; i < 8; i++) acc[i] = 0.f;

    const int e0 = g_rowptr[warp], e1 = g_rowptr[warp + 1];
    int e = e0;

    #define LOADKV(S, KK, VV)                                                  \
        {                                                                      \
            const __half* p_ = kv + (size_t)(S) * 512 + ch;                    \
            KK = *(const uint4*)p_;                                            \
            VV = *(const uint4*)(p_ + 256);                                    \
        }
    #define DOT8(KK, P)                                                        \
        {                                                                      \
            float2 h0_ = __half22float2(*(__half2*)&KK.x);                     \
            float2 h1_ = __half22float2(*(__half2*)&KK.y);                     \
            float2 h2_ = __half22float2(*(__half2*)&KK.z);                     \
            float2 h3_ = __half22float2(*(__half2*)&KK.w);                     \
            P = q0.x*h0_.x + q0.y*h0_.y + q0.z*h1_.x + q0.w*h1_.y              \
              + q1.x*h2_.x + q1.y*h2_.y + q1.z*h3_.x + q1.w*h3_.y;             \
        }
    #define ACCV(VV, PE)                                                       \
        {                                                                      \
            float2 h0_ = __half22float2(*(__half2*)&VV.x);                     \
            float2 h1_ = __half22float2(*(__half2*)&VV.y);                     \
            float2 h2_ = __half22float2(*(__half2*)&VV.z);                     \
            float2 h3_ = __half22float2(*(__half2*)&VV.w);                     \
            acc[0] += PE * h0_.x; acc[1] += PE * h0_.y;                        \
            acc[2] += PE * h1_.x; acc[3] += PE * h1_.y;                        \
            acc[4] += PE * h2_.x; acc[5] += PE * h2_.y;                        \
            acc[6] += PE * h3_.x; acc[7] += PE * h3_.y;                        \
        }

    for (; e + 3 < e1; e += 4) {
        int s0 = g_col[e], s1 = g_col[e + 1], s2 = g_col[e + 2], s3 = g_col[e + 3];
        uint4 k0v, k1v, k2v, k3v, v0v, v1v, v2v, v3v;
        LOADKV(s0, k0v, v0v);
        LOADKV(s1, k1v, v1v);
        LOADKV(s2, k2v, v2v);
        LOADKV(s3, k3v, v3v);

        float p0, p1, p2, p3;
        DOT8(k0v, p0);
        DOT8(k1v, p1);
        DOT8(k2v, p2);
        DOT8(k3v, p3);
        p0 += __shfl_xor_sync(0xffffffff, p0, 1);
        p1 += __shfl_xor_sync(0xffffffff, p1, 1);
        p2 += __shfl_xor_sync(0xffffffff, p2, 1);
        p3 += __shfl_xor_sync(0xffffffff, p3, 1);
        p0 += __shfl_xor_sync(0xffffffff, p0, 2);
        p1 += __shfl_xor_sync(0xffffffff, p1, 2);
        p2 += __shfl_xor_sync(0xffffffff, p2, 2);
        p3 += __shfl_xor_sync(0xffffffff, p3, 2);
        p0 += __shfl_xor_sync(0xffffffff, p0, 4);
        p1 += __shfl_xor_sync(0xffffffff, p1, 4);
        p2 += __shfl_xor_sync(0xffffffff, p2, 4);
        p3 += __shfl_xor_sync(0xffffffff, p3, 4);

        float pe0 = __expf(fminf(p0 * SCALE, 85.f));
        float pe1 = __expf(fminf(p1 * SCALE, 85.f));
        float pe2 = __expf(fminf(p2 * SCALE, 85.f));
        float pe3 = __expf(fminf(p3 * SCALE, 85.f));
        d += pe0 + pe1 + pe2 + pe3;
        ACCV(v0v, pe0);
        ACCV(v1v, pe1);
        ACCV(v2v, pe2);
        ACCV(v3v, pe3);
    }

    for (; e < e1; e++) {
        int s0 = g_col[e];
        uint4 kk, vv;
        LOADKV(s0, kk, vv);
        float p;
        DOT8(kk, p);
        p += __shfl_xor_sync(0xffffffff, p, 1);
        p += __shfl_xor_sync(0xffffffff, p, 2);
        p += __shfl_xor_sync(0xffffffff, p, 4);
        float pe = __expf(fminf(p * SCALE, 85.f));
        d += pe;
        ACCV(vv, pe);
    }

    float inv = (d > 0.f) ? 1.f / d : 0.f;
    uint4 sr = *(const uint4*)(nb + 256 + ch);
    float2 sa = __half22float2(*(__half2*)&sr.x);
    float2 sb = __half22float2(*(__half2*)&sr.y);
    float2 sc = __half22float2(*(__half2*)&sr.z);
    float2 sd = __half22float2(*(__half2*)&sr.w);

    float4 o0, o1;
    o0.x = fmaxf(acc[0] * inv + sa.x, 0.f);
    o0.y = fmaxf(acc[1] * inv + sa.y, 0.f);
    o0.z = fmaxf(acc[2] * inv + sb.x, 0.f);
    o0.w = fmaxf(acc[3] * inv + sb.y, 0.f);
    o1.x = fmaxf(acc[4] * inv + sc.x, 0.f);
    o1.y = fmaxf(acc[5] * inv + sc.y, 0.f);
    o1.z = fmaxf(acc[6] * inv + sd.x, 0.f);
    o1.w = fmaxf(acc[7] * inv + sd.y, 0.f);

    if (ah) {
        uint4 hp;
        *(__half2*)&hp.x = __floats2half2_rn(o0.x, o0.y);
        *(__half2*)&hp.y = __floats2half2_rn(o0.z, o0.w);
        *(__half2*)&hp.z = __floats2half2_rn(o1.x, o1.y);
        *(__half2*)&hp.w = __floats2half2_rn(o1.z, o1.w);
        *(uint4*)(ah + (size_t)warp * 256 + ch) = hp;
    }

    if (out) {
        float* op = out + (size_t)warp * 256 + ch;
        *(float4*)op       = o0;
        *(float4*)(op + 4) = o1;
    }
}

// ---------------- launch ------------------------------------------------------
extern "C" void kernel_launch(void* const* d_in, const int* in_sizes, int n_in,
                              void* d_out, int out_size) {
    const float* x   = (const float*)d_in[0];
    const int*   ei  = (const int*)d_in[1];
    const float* Wq  = (const float*)d_in[2];
    const float* bq  = (const float*)d_in[3];
    const float* Wk  = (const float*)d_in[4];
    const float* bk  = (const float*)d_in[5];
    const float* Wv  = (const float*)d_in[6];
    const float* bv  = (const float*)d_in[7];
    const float* Ws  = (const float*)d_in[8];
    const float* bs  = (const float*)d_in[9];
    float* out = (float*)d_out;

    __half *qsp, *kvp, *ah, *wh;
    cudaGetSymbolAddress((void**)&qsp, g_qs);
    cudaGetSymbolAddress((void**)&kvp, g_kv);
    cudaGetSymbolAddress((void**)&ah,  g_Ah);
    cudaGetSymbolAddress((void**)&wh,  g_Wh);

    static bool init_done = false;
    static cudaStream_t s_aux;
    static cudaEvent_t ev_fork, ev_join, ev_w;
    if (!init_done) {
        cudaFuncSetAttribute(gemm_qkvs_kernel,
                             cudaFuncAttributeMaxDynamicSharedMemorySize, GEMM_SMEM);
        cudaStreamCreateWithFlags(&s_aux, cudaStreamNonBlocking);
        cudaEventCreateWithFlags(&ev_fork, cudaEventDisableTiming);
        cudaEventCreateWithFlags(&ev_join, cudaEventDisableTiming);
        cudaEventCreateWithFlags(&ev_w,    cudaEventDisableTiming);
        init_done = true;
    }

    const int SCAN_BLOCKS = (NN + 1023) / 1024;   // 49

    // fork: weight convert + CSR build on aux stream
    cudaEventRecord(ev_fork, 0);
    cudaStreamWaitEvent(s_aux, ev_fork, 0);

    convert_w_kernel<<<(LL * 4 * 65536 + 255) / 256, 256, 0, s_aux>>>(Wq, Wk, Wv, Ws, wh);
    cudaEventRecord(ev_w, s_aux);
    zero_counts_kernel<<<(NN + 255) / 256, 256, 0, s_aux>>>();
    count_dst_kernel<<<(EE + 255) / 256, 256, 0, s_aux>>>(ei);
    scan1_kernel<<<SCAN_BLOCKS, 1024, 0, s_aux>>>();
    scan2_kernel<<<1, 32, 0, s_aux>>>(SCAN_BLOCKS);
    scan3_kernel<<<SCAN_BLOCKS, 1024, 0, s_aux>>>();
    fill_csr_kernel<<<(EE + 255) / 256, 256, 0, s_aux>>>(ei);
    cudaEventRecord(ev_join, s_aux);

    // main: feature convert, then layers
    convert_x_kernel<<<(NN * 32 + 255) / 256, 256>>>(x, ah);
    cudaStreamWaitEvent(0, ev_w, 0);   // weights ready before GEMM0

    dim3 gemm_grid(8, (NN + BM - 1) / BM);
    int edge_blocks = (NN + 7) / 8;

    for (int l = 0; l < LL; l++) {
        gemm_qkvs_kernel<<<gemm_grid, 256, GEMM_SMEM>>>(
            ah, wh + (size_t)l * 4 * 65536,
            bq + l * HC, bk + l * HC, bv + l * HC, bs + l * HC,
            qsp, kvp, NN);

        if (l == 0) cudaStreamWaitEvent(0, ev_join, 0);   // CSR ready before first edge pass

        float* hout = (l == LL - 1) ? out : nullptr;
        __half* hah = (l == LL - 1) ? nullptr : ah;       // last layer: skip dead ah write
        edge_attn_kernel<<<edge_blocks, 256>>>(qsp, kvp, hout, hah);
    }
}